// round 5
// baseline (speedup 1.0000x reference)
#include <cuda_runtime.h>
#include <cuda_fp16.h>
#include <cstdint>

#define DIM 128
#define MAXN 50176
#define SLOTS 128
#define SLOPE 0.2f

typedef unsigned long long u64;

// ---------------- scratch (static device memory; allocation-free) ----------------
__device__ __align__(16) float  g_att[2 * DIM + 8];
__device__ __align__(16) float  g_s1[MAXN];
__device__ __align__(16) float  g_s2[MAXN];
__device__ __align__(16) float  g_agg[(size_t)MAXN * DIM];
__device__ __align__(16) __half g_featH[(size_t)MAXN * DIM];   // fp16 gather table
__device__ __align__(16) int    g_counts[MAXN];                // self-zeroing
__device__ __align__(16) u64    g_bucket[(size_t)MAXN * SLOTS];

// ---------------- f32x2 helpers ----------------
__device__ __forceinline__ void fma2(u64& d, u64 a, u64 b) {
    asm("fma.rn.f32x2 %0, %1, %2, %0;" : "+l"(d) : "l"(a), "l"(b));
}
__device__ __forceinline__ u64 packdup(float x) {
    u64 r;
    unsigned int xi = __float_as_uint(x);
    asm("mov.b64 %0, {%1, %1};" : "=l"(r) : "r"(xi));
    return r;
}
__device__ __forceinline__ void unpack2(u64 v, float& lo, float& hi) {
    unsigned int a, b;
    asm("mov.b64 {%0, %1}, %2;" : "=r"(a), "=r"(b) : "l"(v));
    lo = __uint_as_float(a);
    hi = __uint_as_float(b);
}
__device__ __forceinline__ float lrelu(float x) { return x > 0.f ? x : SLOPE * x; }

// ---------------- K1: v1 = Watt@a1, v2 = Watt@a2, c = b_att·a ----------------
__global__ void k_att_prep(const float* __restrict__ Watt_w,
                           const float* __restrict__ Watt_b,
                           const float* __restrict__ a) {
    int k = threadIdx.x;
    float v1 = 0.f, v2 = 0.f;
    #pragma unroll 8
    for (int j = 0; j < DIM; j++) {
        float w = Watt_w[k * DIM + j];
        v1 += w * a[j];
        v2 += w * a[DIM + j];
    }
    g_att[k] = v1;
    g_att[DIM + k] = v2;

    __shared__ float sc1[DIM], sc2[DIM];
    sc1[k] = Watt_b[k] * a[k];
    sc2[k] = Watt_b[k] * a[DIM + k];
    __syncthreads();
    for (int s = 64; s > 0; s >>= 1) {
        if (k < s) { sc1[k] += sc1[k + s]; sc2[k] += sc2[k + s]; }
        __syncthreads();
    }
    if (k == 0) { g_att[2 * DIM] = sc1[0]; g_att[2 * DIM + 1] = sc2[0]; }
}

// ---------------- K2: scores s1,s2 + emit fp16 feature copy ----------------
__global__ void k_node_scores(const float* __restrict__ feat, int N) {
    int warp = (blockIdx.x * blockDim.x + threadIdx.x) >> 5;
    int lane = threadIdx.x & 31;
    if (warp >= N) return;
    float4 f  = *(const float4*)(feat + (size_t)warp * DIM + lane * 4);

    // fp16 copy (4 halves = 8B per lane, coalesced 256B per warp)
    __half2 h0 = __floats2half2_rn(f.x, f.y);
    __half2 h1 = __floats2half2_rn(f.z, f.w);
    uint2 raw;
    raw.x = *(unsigned*)&h0;
    raw.y = *(unsigned*)&h1;
    *(uint2*)(g_featH + (size_t)warp * DIM + lane * 4) = raw;

    float4 v1 = *(const float4*)(g_att + lane * 4);
    float4 v2 = *(const float4*)(g_att + DIM + lane * 4);
    float d1 = f.x * v1.x + f.y * v1.y + f.z * v1.z + f.w * v1.w;
    float d2 = f.x * v2.x + f.y * v2.y + f.z * v2.z + f.w * v2.w;
    #pragma unroll
    for (int o = 16; o > 0; o >>= 1) {
        d1 += __shfl_xor_sync(0xffffffffu, d1, o);
        d2 += __shfl_xor_sync(0xffffffffu, d2, o);
    }
    if (lane == 0) {
        g_s1[warp] = d1 + g_att[2 * DIM];
        g_s2[warp] = d2 + g_att[2 * DIM + 1];
    }
}

// ---------------- K3: fill per-dst buckets ----------------
__global__ void k_fill(const int* __restrict__ idx, int E) {
    int e = blockIdx.x * blockDim.x + threadIdx.x;
    if (e >= E) return;
    int s = idx[e];
    int d = idx[E + e];
    float w = __expf(lrelu(g_s1[s] + g_s2[d]));
    int pos = atomicAdd(&g_counts[d], 1);
    pos = min(pos, SLOTS - 1);
    g_bucket[(size_t)d * SLOTS + pos] = ((u64)__float_as_uint(w) << 32) | (unsigned)s;
}

// ---------------- K4 (PROFILED SLOT): per-dst aggregation over fp16 table --------
__global__ void __launch_bounds__(256) k_aggregate(int N) {
    int d = (blockIdx.x * blockDim.x + threadIdx.x) >> 5;
    int lane = threadIdx.x & 31;
    if (d >= N) return;
    int cnt = min(g_counts[d], SLOTS);
    const u64* B = g_bucket + (size_t)d * SLOTS;

    float4 acc = make_float4(0.f, 0.f, 0.f, 0.f);
    float wsum = 0.f;

    int j = 0;
    for (; j + 8 <= cnt; j += 8) {
        u64 e[8];
        #pragma unroll
        for (int t = 0; t < 8; t++) e[t] = B[j + t];
        uint2 raw[8];
        #pragma unroll
        for (int t = 0; t < 8; t++) {
            int s = (int)(unsigned)e[t];
            raw[t] = *(const uint2*)(g_featH + (size_t)s * DIM + lane * 4);
        }
        #pragma unroll
        for (int t = 0; t < 8; t++) {
            float w = __uint_as_float((unsigned)(e[t] >> 32));
            float2 a = __half22float2(*(__half2*)&raw[t].x);
            float2 b = __half22float2(*(__half2*)&raw[t].y);
            acc.x += w * a.x; acc.y += w * a.y;
            acc.z += w * b.x; acc.w += w * b.y;
            wsum += w;
        }
    }
    for (; j < cnt; j++) {
        u64 ej = B[j];
        int s = (int)(unsigned)ej;
        float w = __uint_as_float((unsigned)(ej >> 32));
        uint2 raw = *(const uint2*)(g_featH + (size_t)s * DIM + lane * 4);
        float2 a = __half22float2(*(__half2*)&raw.x);
        float2 b = __half22float2(*(__half2*)&raw.y);
        acc.x += w * a.x; acc.y += w * a.y;
        acc.z += w * b.x; acc.w += w * b.y;
        wsum += w;
    }

    if (lane == 0) g_counts[d] = 0;

    float inv = 1.f / (wsum + 1e-9f);
    float4 o = make_float4(acc.x * inv, acc.y * inv, acc.z * inv, acc.w * inv);
    *(float4*)(g_agg + (size_t)d * DIM + lane * 4) = o;
}

// ---------------- K5: fused double GEMM (512 threads, 2 rows/thread) ----------------
__global__ void __launch_bounds__(512) k_gemm_fused(const float* __restrict__ feat,
                                                    const float* __restrict__ W1,
                                                    const float* __restrict__ b1,
                                                    const float* __restrict__ W2,
                                                    const float* __restrict__ b2,
                                                    float* __restrict__ out,
                                                    int N) {
    extern __shared__ float sm[];
    float* sW1 = sm;                             // 128*128
    float* sW2 = sm + DIM * DIM;                 // 128*128
    float* sA  = sm + 2 * DIM * DIM;             // 64*128 (agg tile, then prod)
    float* sS  = sm + 2 * DIM * DIM + 64 * DIM;  // 64*128 (sum tile)

    int tid = threadIdx.x;
    int row0 = blockIdx.x * 64;

    #pragma unroll
    for (int i = tid; i < DIM * DIM / 4; i += 512) {
        ((float4*)sW1)[i] = ((const float4*)W1)[i];
        ((float4*)sW2)[i] = ((const float4*)W2)[i];
    }
    for (int i = tid; i < 64 * 32; i += 512) {
        int r = i >> 5, c4 = (i & 31) << 2;
        int gr = row0 + r;
        float4 v = make_float4(0.f, 0.f, 0.f, 0.f);
        if (gr < N) v = *(const float4*)(g_agg + (size_t)gr * DIM + c4);
        *(float4*)(sA + r * DIM + c4) = v;
    }
    __syncthreads();

    int tx = tid & 15, ty = tid >> 4;  // ty: 0..31
    int c0 = tx * 8, r0 = ty * 2;

    // ---- GEMM1: hneigh = agg @ W1 ----
    u64 acc[2][4];
    #pragma unroll
    for (int i = 0; i < 2; i++)
        #pragma unroll
        for (int j = 0; j < 4; j++) acc[i][j] = 0ull;

    #pragma unroll 4
    for (int k = 0; k < DIM; k++) {
        u64 w0 = *(const u64*)(sW1 + k * DIM + c0 + 0);
        u64 w1 = *(const u64*)(sW1 + k * DIM + c0 + 2);
        u64 w2 = *(const u64*)(sW1 + k * DIM + c0 + 4);
        u64 w3 = *(const u64*)(sW1 + k * DIM + c0 + 6);
        #pragma unroll
        for (int i = 0; i < 2; i++) {
            u64 ai = packdup(sA[(r0 + i) * DIM + k]);
            fma2(acc[i][0], ai, w0);
            fma2(acc[i][1], ai, w1);
            fma2(acc[i][2], ai, w2);
            fma2(acc[i][3], ai, w3);
        }
    }

    float hn[2][8];
    float bb[8];
    #pragma unroll
    for (int c = 0; c < 8; c++) bb[c] = b1[c0 + c];
    #pragma unroll
    for (int i = 0; i < 2; i++) {
        #pragma unroll
        for (int j = 0; j < 4; j++) unpack2(acc[i][j], hn[i][2 * j], hn[i][2 * j + 1]);
        #pragma unroll
        for (int c = 0; c < 8; c++) hn[i][c] += bb[c];
    }

    __syncthreads();  // done reading sA as agg tile

    // ---- build prod (sA) and sum (sS) tiles ----
    #pragma unroll
    for (int i = 0; i < 2; i++) {
        int gr = row0 + r0 + i;
        float4 f0 = make_float4(0.f, 0.f, 0.f, 0.f);
        float4 f1 = make_float4(0.f, 0.f, 0.f, 0.f);
        if (gr < N) {
            f0 = *(const float4*)(feat + (size_t)gr * DIM + c0 + 0);
            f1 = *(const float4*)(feat + (size_t)gr * DIM + c0 + 4);
        }
        float* pP = sA + (r0 + i) * DIM + c0;
        float* pS = sS + (r0 + i) * DIM + c0;
        pP[0] = f0.x * hn[i][0]; pP[1] = f0.y * hn[i][1];
        pP[2] = f0.z * hn[i][2]; pP[3] = f0.w * hn[i][3];
        pP[4] = f1.x * hn[i][4]; pP[5] = f1.y * hn[i][5];
        pP[6] = f1.z * hn[i][6]; pP[7] = f1.w * hn[i][7];
        pS[0] = f0.x + hn[i][0]; pS[1] = f0.y + hn[i][1];
        pS[2] = f0.z + hn[i][2]; pS[3] = f0.w + hn[i][3];
        pS[4] = f1.x + hn[i][4]; pS[5] = f1.y + hn[i][5];
        pS[6] = f1.z + hn[i][6]; pS[7] = f1.w + hn[i][7];
    }
    __syncthreads();

    // ---- GEMM2: prod @ W2 ----
    #pragma unroll
    for (int i = 0; i < 2; i++)
        #pragma unroll
        for (int j = 0; j < 4; j++) acc[i][j] = 0ull;

    #pragma unroll 4
    for (int k = 0; k < DIM; k++) {
        u64 w0 = *(const u64*)(sW2 + k * DIM + c0 + 0);
        u64 w1 = *(const u64*)(sW2 + k * DIM + c0 + 2);
        u64 w2 = *(const u64*)(sW2 + k * DIM + c0 + 4);
        u64 w3 = *(const u64*)(sW2 + k * DIM + c0 + 6);
        #pragma unroll
        for (int i = 0; i < 2; i++) {
            u64 ai = packdup(sA[(r0 + i) * DIM + k]);
            fma2(acc[i][0], ai, w0);
            fma2(acc[i][1], ai, w1);
            fma2(acc[i][2], ai, w2);
            fma2(acc[i][3], ai, w3);
        }
    }

    // ---- epilogue ----
    #pragma unroll
    for (int c = 0; c < 8; c++) bb[c] = b2[c0 + c];
    #pragma unroll
    for (int i = 0; i < 2; i++) {
        int gr = row0 + r0 + i;
        if (gr >= N) continue;
        float o[8];
        #pragma unroll
        for (int j = 0; j < 4; j++) unpack2(acc[i][j], o[2 * j], o[2 * j + 1]);
        const float* pS = sS + (r0 + i) * DIM + c0;
        #pragma unroll
        for (int c = 0; c < 8; c++) o[c] = lrelu(o[c] + bb[c] + pS[c]);
        float* dst = out + (size_t)gr * DIM + c0;
        *(float4*)(dst + 0) = make_float4(o[0], o[1], o[2], o[3]);
        *(float4*)(dst + 4) = make_float4(o[4], o[5], o[6], o[7]);
    }
}

// ---------------- launch ----------------
extern "C" void kernel_launch(void* const* d_in, const int* in_sizes, int n_in,
                              void* d_out, int out_size) {
    const int*   indices  = (const int*)d_in[0];
    const float* features = (const float*)d_in[1];
    const float* W1_w   = (const float*)d_in[3];
    const float* W1_b   = (const float*)d_in[4];
    const float* W2_w   = (const float*)d_in[5];
    const float* W2_b   = (const float*)d_in[6];
    const float* Watt_w = (const float*)d_in[7];
    const float* Watt_b = (const float*)d_in[8];
    const float* a_vec  = (const float*)d_in[9];

    int E = in_sizes[0] / 2;
    int N = in_sizes[1] / DIM;

    const int SMEMF = (2 * DIM * DIM + 2 * 64 * DIM) * 4;  // 192KB
    cudaFuncSetAttribute((const void*)k_gemm_fused,
                         cudaFuncAttributeMaxDynamicSharedMemorySize, SMEMF);

    float* out = (float*)d_out;

    // slot 1
    k_att_prep<<<1, DIM>>>(Watt_w, Watt_b, a_vec);
    // slot 2
    k_node_scores<<<(N * 32 + 255) / 256, 256>>>(features, N);
    // slot 3
    k_fill<<<(E + 255) / 256, 256>>>(indices, E);
    // slot 4  (profiled)
    k_aggregate<<<(N * 32 + 255) / 256, 256>>>(N);
    // slot 5
    k_gemm_fused<<<(N + 63) / 64, 512, SMEMF>>>(features, W1_w, W1_b, W2_w, W2_b, out, N);
}

// round 6
// speedup vs baseline: 1.3597x; 1.3597x over previous
#include <cuda_runtime.h>
#include <cuda_fp16.h>
#include <cstdint>

#define DIM 128
#define MAXN 50176
#define SLOTS 128
#define SLOPE 0.2f

typedef unsigned long long u64;

// ---------------- scratch (static device memory; allocation-free) ----------------
__device__ __align__(16) float  g_att[2 * DIM + 8];
__device__ __align__(16) float  g_s1[MAXN];
__device__ __align__(16) float  g_s2[MAXN];
__device__ __align__(16) float  g_agg[(size_t)MAXN * DIM];
__device__ __align__(16) __half g_featH[(size_t)MAXN * DIM];   // fp16 gather table
__device__ __align__(16) int    g_counts[MAXN];                // self-zeroing
__device__ __align__(16) u64    g_bucket[(size_t)MAXN * SLOTS];

// ---------------- f32x2 helpers ----------------
__device__ __forceinline__ void fma2(u64& d, u64 a, u64 b) {
    asm("fma.rn.f32x2 %0, %1, %2, %0;" : "+l"(d) : "l"(a), "l"(b));
}
__device__ __forceinline__ u64 packdup(float x) {
    u64 r;
    unsigned int xi = __float_as_uint(x);
    asm("mov.b64 %0, {%1, %1};" : "=l"(r) : "r"(xi));
    return r;
}
__device__ __forceinline__ void unpack2(u64 v, float& lo, float& hi) {
    unsigned int a, b;
    asm("mov.b64 {%0, %1}, %2;" : "=r"(a), "=r"(b) : "l"(v));
    lo = __uint_as_float(a);
    hi = __uint_as_float(b);
}
__device__ __forceinline__ float lrelu(float x) { return x > 0.f ? x : SLOPE * x; }

// ---------------- K1: v1 = Watt@a1, v2 = Watt@a2, c = b_att·a ----------------
__global__ void k_att_prep(const float* __restrict__ Watt_w,
                           const float* __restrict__ Watt_b,
                           const float* __restrict__ a) {
    int k = threadIdx.x;
    float v1 = 0.f, v2 = 0.f;
    #pragma unroll 8
    for (int j = 0; j < DIM; j++) {
        float w = Watt_w[k * DIM + j];
        v1 += w * a[j];
        v2 += w * a[DIM + j];
    }
    g_att[k] = v1;
    g_att[DIM + k] = v2;

    __shared__ float sc1[DIM], sc2[DIM];
    sc1[k] = Watt_b[k] * a[k];
    sc2[k] = Watt_b[k] * a[DIM + k];
    __syncthreads();
    for (int s = 64; s > 0; s >>= 1) {
        if (k < s) { sc1[k] += sc1[k + s]; sc2[k] += sc2[k + s]; }
        __syncthreads();
    }
    if (k == 0) { g_att[2 * DIM] = sc1[0]; g_att[2 * DIM + 1] = sc2[0]; }
}

// ---------------- K2: scores s1,s2 + emit fp16 feature copy ----------------
__global__ void k_node_scores(const float* __restrict__ feat, int N) {
    int warp = (blockIdx.x * blockDim.x + threadIdx.x) >> 5;
    int lane = threadIdx.x & 31;
    if (warp >= N) return;
    float4 f  = *(const float4*)(feat + (size_t)warp * DIM + lane * 4);

    __half2 h0 = __floats2half2_rn(f.x, f.y);
    __half2 h1 = __floats2half2_rn(f.z, f.w);
    uint2 raw;
    raw.x = *(unsigned*)&h0;
    raw.y = *(unsigned*)&h1;
    *(uint2*)(g_featH + (size_t)warp * DIM + lane * 4) = raw;

    float4 v1 = *(const float4*)(g_att + lane * 4);
    float4 v2 = *(const float4*)(g_att + DIM + lane * 4);
    float d1 = f.x * v1.x + f.y * v1.y + f.z * v1.z + f.w * v1.w;
    float d2 = f.x * v2.x + f.y * v2.y + f.z * v2.z + f.w * v2.w;
    #pragma unroll
    for (int o = 16; o > 0; o >>= 1) {
        d1 += __shfl_xor_sync(0xffffffffu, d1, o);
        d2 += __shfl_xor_sync(0xffffffffu, d2, o);
    }
    if (lane == 0) {
        g_s1[warp] = d1 + g_att[2 * DIM];
        g_s2[warp] = d2 + g_att[2 * DIM + 1];
    }
}

// ---------------- K3: fill per-dst buckets ----------------
__global__ void k_fill(const int* __restrict__ idx, int E) {
    int e = blockIdx.x * blockDim.x + threadIdx.x;
    if (e >= E) return;
    int s = idx[e];
    int d = idx[E + e];
    float w = __expf(lrelu(g_s1[s] + g_s2[d]));
    int pos = atomicAdd(&g_counts[d], 1);
    pos = min(pos, SLOTS - 1);
    g_bucket[(size_t)d * SLOTS + pos] = ((u64)__float_as_uint(w) << 32) | (unsigned)s;
}

// ---------------- K4 (PROFILED SLOT): per-dst aggregation over fp16 table --------
__global__ void __launch_bounds__(256) k_aggregate(int N) {
    int d = (blockIdx.x * blockDim.x + threadIdx.x) >> 5;
    int lane = threadIdx.x & 31;
    if (d >= N) return;
    int cnt = min(g_counts[d], SLOTS);
    const u64* B = g_bucket + (size_t)d * SLOTS;
    // pre-biased base: row gather becomes  base + (s << 8) bytes
    const char* featB = (const char*)g_featH + lane * 8;

    float4 acc = make_float4(0.f, 0.f, 0.f, 0.f);
    float wsum = 0.f;

    int j = 0;
    for (; j + 8 <= cnt; j += 8) {
        u64 e[8];
        #pragma unroll
        for (int t = 0; t < 8; t++) e[t] = B[j + t];
        uint2 raw[8];
        #pragma unroll
        for (int t = 0; t < 8; t++) {
            unsigned s = (unsigned)e[t];
            raw[t] = *(const uint2*)(featB + ((size_t)s << 8));
        }
        #pragma unroll
        for (int t = 0; t < 8; t++) {
            float w = __uint_as_float((unsigned)(e[t] >> 32));
            float2 a = __half22float2(*(__half2*)&raw[t].x);
            float2 b = __half22float2(*(__half2*)&raw[t].y);
            acc.x += w * a.x; acc.y += w * a.y;
            acc.z += w * b.x; acc.w += w * b.y;
            wsum += w;
        }
    }
    for (; j < cnt; j++) {
        u64 ej = B[j];
        unsigned s = (unsigned)ej;
        float w = __uint_as_float((unsigned)(ej >> 32));
        uint2 raw = *(const uint2*)(featB + ((size_t)s << 8));
        float2 a = __half22float2(*(__half2*)&raw.x);
        float2 b = __half22float2(*(__half2*)&raw.y);
        acc.x += w * a.x; acc.y += w * a.y;
        acc.z += w * b.x; acc.w += w * b.y;
        wsum += w;
    }

    if (lane == 0) g_counts[d] = 0;

    float inv = 1.f / (wsum + 1e-9f);
    float4 o = make_float4(acc.x * inv, acc.y * inv, acc.z * inv, acc.w * inv);
    *(float4*)(g_agg + (size_t)d * DIM + lane * 4) = o;
}

// ---------------- K5: fused double GEMM (256 threads, 4 rows/thread — R4 config) --
__global__ void __launch_bounds__(256) k_gemm_fused(const float* __restrict__ feat,
                                                    const float* __restrict__ W1,
                                                    const float* __restrict__ b1,
                                                    const float* __restrict__ W2,
                                                    const float* __restrict__ b2,
                                                    float* __restrict__ out,
                                                    int N) {
    extern __shared__ float sm[];
    float* sW1 = sm;                             // 128*128
    float* sW2 = sm + DIM * DIM;                 // 128*128
    float* sA  = sm + 2 * DIM * DIM;             // 64*128 (agg tile, then prod)
    float* sS  = sm + 2 * DIM * DIM + 64 * DIM;  // 64*128 (sum tile)

    int tid = threadIdx.x;
    int row0 = blockIdx.x * 64;

    #pragma unroll
    for (int i = tid; i < DIM * DIM / 4; i += 256) {
        ((float4*)sW1)[i] = ((const float4*)W1)[i];
        ((float4*)sW2)[i] = ((const float4*)W2)[i];
    }
    for (int i = tid; i < 64 * 32; i += 256) {
        int r = i >> 5, c4 = (i & 31) << 2;
        int gr = row0 + r;
        float4 v = make_float4(0.f, 0.f, 0.f, 0.f);
        if (gr < N) v = *(const float4*)(g_agg + (size_t)gr * DIM + c4);
        *(float4*)(sA + r * DIM + c4) = v;
    }
    __syncthreads();

    int tx = tid & 15, ty = tid >> 4;
    int c0 = tx * 8, r0 = ty * 4;

    // ---- GEMM1: hneigh = agg @ W1 ----
    u64 acc[4][4];
    #pragma unroll
    for (int i = 0; i < 4; i++)
        #pragma unroll
        for (int j = 0; j < 4; j++) acc[i][j] = 0ull;

    #pragma unroll 4
    for (int k = 0; k < DIM; k++) {
        u64 w0 = *(const u64*)(sW1 + k * DIM + c0 + 0);
        u64 w1 = *(const u64*)(sW1 + k * DIM + c0 + 2);
        u64 w2 = *(const u64*)(sW1 + k * DIM + c0 + 4);
        u64 w3 = *(const u64*)(sW1 + k * DIM + c0 + 6);
        #pragma unroll
        for (int i = 0; i < 4; i++) {
            u64 ai = packdup(sA[(r0 + i) * DIM + k]);
            fma2(acc[i][0], ai, w0);
            fma2(acc[i][1], ai, w1);
            fma2(acc[i][2], ai, w2);
            fma2(acc[i][3], ai, w3);
        }
    }

    float hn[4][8];
    float bb[8];
    #pragma unroll
    for (int c = 0; c < 8; c++) bb[c] = b1[c0 + c];
    #pragma unroll
    for (int i = 0; i < 4; i++) {
        #pragma unroll
        for (int j = 0; j < 4; j++) unpack2(acc[i][j], hn[i][2 * j], hn[i][2 * j + 1]);
        #pragma unroll
        for (int c = 0; c < 8; c++) hn[i][c] += bb[c];
    }

    __syncthreads();  // done reading sA as agg tile

    // ---- build prod (sA) and sum (sS) tiles ----
    #pragma unroll
    for (int i = 0; i < 4; i++) {
        int gr = row0 + r0 + i;
        float4 f0 = make_float4(0.f, 0.f, 0.f, 0.f);
        float4 f1 = make_float4(0.f, 0.f, 0.f, 0.f);
        if (gr < N) {
            f0 = *(const float4*)(feat + (size_t)gr * DIM + c0 + 0);
            f1 = *(const float4*)(feat + (size_t)gr * DIM + c0 + 4);
        }
        float* pP = sA + (r0 + i) * DIM + c0;
        float* pS = sS + (r0 + i) * DIM + c0;
        pP[0] = f0.x * hn[i][0]; pP[1] = f0.y * hn[i][1];
        pP[2] = f0.z * hn[i][2]; pP[3] = f0.w * hn[i][3];
        pP[4] = f1.x * hn[i][4]; pP[5] = f1.y * hn[i][5];
        pP[6] = f1.z * hn[i][6]; pP[7] = f1.w * hn[i][7];
        pS[0] = f0.x + hn[i][0]; pS[1] = f0.y + hn[i][1];
        pS[2] = f0.z + hn[i][2]; pS[3] = f0.w + hn[i][3];
        pS[4] = f1.x + hn[i][4]; pS[5] = f1.y + hn[i][5];
        pS[6] = f1.z + hn[i][6]; pS[7] = f1.w + hn[i][7];
    }
    __syncthreads();

    // ---- GEMM2: prod @ W2 ----
    #pragma unroll
    for (int i = 0; i < 4; i++)
        #pragma unroll
        for (int j = 0; j < 4; j++) acc[i][j] = 0ull;

    #pragma unroll 4
    for (int k = 0; k < DIM; k++) {
        u64 w0 = *(const u64*)(sW2 + k * DIM + c0 + 0);
        u64 w1 = *(const u64*)(sW2 + k * DIM + c0 + 2);
        u64 w2 = *(const u64*)(sW2 + k * DIM + c0 + 4);
        u64 w3 = *(const u64*)(sW2 + k * DIM + c0 + 6);
        #pragma unroll
        for (int i = 0; i < 4; i++) {
            u64 ai = packdup(sA[(r0 + i) * DIM + k]);
            fma2(acc[i][0], ai, w0);
            fma2(acc[i][1], ai, w1);
            fma2(acc[i][2], ai, w2);
            fma2(acc[i][3], ai, w3);
        }
    }

    // ---- epilogue ----
    #pragma unroll
    for (int c = 0; c < 8; c++) bb[c] = b2[c0 + c];
    #pragma unroll
    for (int i = 0; i < 4; i++) {
        int gr = row0 + r0 + i;
        if (gr >= N) continue;
        float o[8];
        #pragma unroll
        for (int j = 0; j < 4; j++) unpack2(acc[i][j], o[2 * j], o[2 * j + 1]);
        const float* pS = sS + (r0 + i) * DIM + c0;
        #pragma unroll
        for (int c = 0; c < 8; c++) o[c] = lrelu(o[c] + bb[c] + pS[c]);
        float* dst = out + (size_t)gr * DIM + c0;
        *(float4*)(dst + 0) = make_float4(o[0], o[1], o[2], o[3]);
        *(float4*)(dst + 4) = make_float4(o[4], o[5], o[6], o[7]);
    }
}

// ---------------- launch ----------------
extern "C" void kernel_launch(void* const* d_in, const int* in_sizes, int n_in,
                              void* d_out, int out_size) {
    const int*   indices  = (const int*)d_in[0];
    const float* features = (const float*)d_in[1];
    const float* W1_w   = (const float*)d_in[3];
    const float* W1_b   = (const float*)d_in[4];
    const float* W2_w   = (const float*)d_in[5];
    const float* W2_b   = (const float*)d_in[6];
    const float* Watt_w = (const float*)d_in[7];
    const float* Watt_b = (const float*)d_in[8];
    const float* a_vec  = (const float*)d_in[9];

    int E = in_sizes[0] / 2;
    int N = in_sizes[1] / DIM;

    const int SMEMF = (2 * DIM * DIM + 2 * 64 * DIM) * 4;  // 192KB
    cudaFuncSetAttribute((const void*)k_gemm_fused,
                         cudaFuncAttributeMaxDynamicSharedMemorySize, SMEMF);

    float* out = (float*)d_out;

    // slot 1
    k_att_prep<<<1, DIM>>>(Watt_w, Watt_b, a_vec);
    // slot 2
    k_node_scores<<<(N * 32 + 255) / 256, 256>>>(features, N);
    // slot 3
    k_fill<<<(E + 255) / 256, 256>>>(indices, E);
    // slot 4  (profiled)
    k_aggregate<<<(N * 32 + 255) / 256, 256>>>(N);
    // slot 5
    k_gemm_fused<<<(N + 63) / 64, 256, SMEMF>>>(features, W1_w, W1_b, W2_w, W2_b, out, N);
}

// round 8
// speedup vs baseline: 2.1825x; 1.6052x over previous
#include <cuda_runtime.h>
#include <cuda_fp16.h>
#include <cstdint>

#define DIM 128
#define MAXN 50176
#define SLOTS 128
#define SLOPE 0.2f
#define PAD 136          // halfs per smem row (272B) — bank-conflict-free ldmatrix
typedef unsigned long long u64;

// ---------------- scratch ----------------
__device__ __align__(16) float  g_att[2 * DIM + 8];
__device__ __align__(16) float  g_s1[MAXN];
__device__ __align__(16) float  g_s2[MAXN];
__device__ __align__(16) __half g_featH[(size_t)MAXN * DIM];
__device__ __align__(16) int    g_counts[MAXN];                // self-zeroing
__device__ __align__(16) u64    g_bucket[(size_t)MAXN * SLOTS];
__device__ __align__(16) __half g_W1T[DIM * PAD];  // W1^T padded: [n][k] = W1[k][n]
__device__ __align__(16) __half g_W2T[DIM * PAD];

__device__ __forceinline__ float lrelu(float x) { return x > 0.f ? x : SLOPE * x; }

__device__ __forceinline__ void mma16816(float* c, const uint32_t* a,
                                         uint32_t b0, uint32_t b1) {
    asm volatile(
        "mma.sync.aligned.m16n8k16.row.col.f32.f16.f16.f32 "
        "{%0,%1,%2,%3}, {%4,%5,%6,%7}, {%8,%9}, {%0,%1,%2,%3};"
        : "+f"(c[0]), "+f"(c[1]), "+f"(c[2]), "+f"(c[3])
        : "r"(a[0]), "r"(a[1]), "r"(a[2]), "r"(a[3]), "r"(b0), "r"(b1));
}
__device__ __forceinline__ void ldmatrix4(uint32_t* a, uint32_t addr) {
    asm volatile("ldmatrix.sync.aligned.m8n8.x4.shared.b16 {%0,%1,%2,%3}, [%4];"
                 : "=r"(a[0]), "=r"(a[1]), "=r"(a[2]), "=r"(a[3]) : "r"(addr));
}

// ---------------- K0: att projection vectors + W^T fp16 tables ----------------
__global__ void k_attw(const float* __restrict__ Watt_w, const float* __restrict__ Watt_b,
                       const float* __restrict__ a,
                       const float* __restrict__ W1_w, const float* __restrict__ W2_w) {
    int tid = threadIdx.x;
    if (blockIdx.x == 0) {
        __shared__ float sc1[DIM], sc2[DIM];
        if (tid < DIM) {
            float v1 = 0.f, v2 = 0.f;
            #pragma unroll 8
            for (int j = 0; j < DIM; j++) {
                float w = Watt_w[tid * DIM + j];
                v1 += w * a[j];
                v2 += w * a[DIM + j];
            }
            g_att[tid] = v1;
            g_att[DIM + tid] = v2;
            sc1[tid] = Watt_b[tid] * a[tid];
            sc2[tid] = Watt_b[tid] * a[DIM + tid];
        }
        __syncthreads();
        for (int s = 64; s > 0; s >>= 1) {
            if (tid < s) { sc1[tid] += sc1[tid + s]; sc2[tid] += sc2[tid + s]; }
            __syncthreads();
        }
        if (tid == 0) { g_att[2 * DIM] = sc1[0]; g_att[2 * DIM + 1] = sc2[0]; }
    } else {
        // W^T tables: Wt[n][k] = W[k][n]
        int base = (blockIdx.x - 1) * 2048 + tid;
        #pragma unroll
        for (int i = 0; i < 8; i++) {
            int e = base + i * 256;
            int wsel = e >> 14;
            int rem = e & 16383;
            int k = rem >> 7, n = rem & 127;
            float v = wsel ? W2_w[rem] : W1_w[rem];
            __half* img = wsel ? g_W2T : g_W1T;
            img[n * PAD + k] = __float2half(v);
        }
    }
}

// ---------------- K1: scores + fp16 feature table ----------------
__global__ void k_node_scores(const float* __restrict__ feat, int N) {
    int warp = (blockIdx.x * blockDim.x + threadIdx.x) >> 5;
    int lane = threadIdx.x & 31;
    if (warp >= N) return;
    float4 f = *(const float4*)(feat + (size_t)warp * DIM + lane * 4);

    __half2 h0 = __floats2half2_rn(f.x, f.y);
    __half2 h1 = __floats2half2_rn(f.z, f.w);
    uint2 raw;
    raw.x = *(unsigned*)&h0;
    raw.y = *(unsigned*)&h1;
    *(uint2*)(g_featH + (size_t)warp * DIM + lane * 4) = raw;

    float4 v1 = *(const float4*)(g_att + lane * 4);
    float4 v2 = *(const float4*)(g_att + DIM + lane * 4);
    float d1 = f.x * v1.x + f.y * v1.y + f.z * v1.z + f.w * v1.w;
    float d2 = f.x * v2.x + f.y * v2.y + f.z * v2.z + f.w * v2.w;
    #pragma unroll
    for (int o = 16; o > 0; o >>= 1) {
        d1 += __shfl_xor_sync(0xffffffffu, d1, o);
        d2 += __shfl_xor_sync(0xffffffffu, d2, o);
    }
    if (lane == 0) {
        g_s1[warp] = d1 + g_att[2 * DIM];
        g_s2[warp] = d2 + g_att[2 * DIM + 1];
    }
}

// ---------------- K2: fill per-dst buckets ----------------
__global__ void k_fill(const int* __restrict__ idx, int E) {
    int e = blockIdx.x * blockDim.x + threadIdx.x;
    if (e >= E) return;
    int s = idx[e];
    int d = idx[E + e];
    float w = __expf(lrelu(g_s1[s] + g_s2[d]));
    int pos = atomicAdd(&g_counts[d], 1);
    pos = min(pos, SLOTS - 1);
    g_bucket[(size_t)d * SLOTS + pos] = ((u64)__float_as_uint(w) << 32) | (unsigned)s;
}

// ---------------- K3: fused aggregate + HMMA GEMM1 + elementwise + GEMM2 ----------
static constexpr int SM_B1 = 0;                    // 512B
static constexpr int SM_B2 = 512;                  // 512B
static constexpr int SM_A  = 1024;                 // 128*PAD halfs = 34816B
static constexpr int SM_W1 = SM_A + 128 * PAD * 2; // 35840
static constexpr int SM_W2 = SM_W1 + 128 * PAD * 2;
static constexpr int SMEMF = SM_W2 + 128 * PAD * 2;  // 105472B

__global__ void __launch_bounds__(512, 1)
k_fused(const float* __restrict__ feat,
        const float* __restrict__ b1, const float* __restrict__ b2,
        float* __restrict__ out, int N) {
    extern __shared__ char sm[];
    uint32_t smb;
    asm("{ .reg .u64 t; cvta.to.shared.u64 t, %1; cvt.u32.u64 %0, t; }" : "=r"(smb) : "l"(sm));
    int tid = threadIdx.x, wid = tid >> 5, lane = tid & 31;
    int row0 = blockIdx.x * 128;

    // stage weight tables + biases
    {
        const uint4* w1 = (const uint4*)g_W1T;
        const uint4* w2 = (const uint4*)g_W2T;
        uint4* s1p = (uint4*)(sm + SM_W1);
        uint4* s2p = (uint4*)(sm + SM_W2);
        #pragma unroll 4
        for (int i = tid; i < 128 * PAD / 8; i += 512) { s1p[i] = w1[i]; s2p[i] = w2[i]; }
        if (tid < 128) {
            ((float*)(sm + SM_B1))[tid] = b1[tid];
            ((float*)(sm + SM_B2))[tid] = b2[tid];
        }
    }

    // ---- phase A: aggregate 8 rows per warp into sA (fp16, padded row-major) ----
    const char* featB = (const char*)g_featH + lane * 8;
    for (int rr = 0; rr < 8; rr++) {
        int r = wid * 8 + rr;
        int d = row0 + r;
        float4 acc = make_float4(0.f, 0.f, 0.f, 0.f);
        float wsum = 0.f;
        if (d < N) {
            int cnt = min(g_counts[d], SLOTS);
            const u64* B = g_bucket + (size_t)d * SLOTS;
            int j = 0;
            for (; j + 8 <= cnt; j += 8) {
                u64 e[8];
                #pragma unroll
                for (int t = 0; t < 8; t++) e[t] = B[j + t];
                uint2 raw[8];
                #pragma unroll
                for (int t = 0; t < 8; t++)
                    raw[t] = *(const uint2*)(featB + ((size_t)(unsigned)e[t] << 8));
                #pragma unroll
                for (int t = 0; t < 8; t++) {
                    float w = __uint_as_float((unsigned)(e[t] >> 32));
                    float2 a = __half22float2(*(__half2*)&raw[t].x);
                    float2 b = __half22float2(*(__half2*)&raw[t].y);
                    acc.x += w * a.x; acc.y += w * a.y;
                    acc.z += w * b.x; acc.w += w * b.y;
                    wsum += w;
                }
            }
            for (; j < cnt; j++) {
                u64 ej = B[j];
                float w = __uint_as_float((unsigned)(ej >> 32));
                uint2 raw = *(const uint2*)(featB + ((size_t)(unsigned)ej << 8));
                float2 a = __half22float2(*(__half2*)&raw.x);
                float2 b = __half22float2(*(__half2*)&raw.y);
                acc.x += w * a.x; acc.y += w * a.y;
                acc.z += w * b.x; acc.w += w * b.y;
                wsum += w;
            }
            if (lane == 0) g_counts[d] = 0;
        }
        float inv = 1.f / (wsum + 1e-9f);
        __half2 p0 = __floats2half2_rn(acc.x * inv, acc.y * inv);
        __half2 p1 = __floats2half2_rn(acc.z * inv, acc.w * inv);
        uint2 pk;
        pk.x = *(unsigned*)&p0;
        pk.y = *(unsigned*)&p1;
        *(uint2*)(sm + SM_A + (r * PAD + lane * 4) * 2) = pk;
    }
    __syncthreads();

    // warp grid 4x4: 32x32 output tile per warp
    int m0 = (wid >> 2) * 32, n0 = (wid & 3) * 32;
    int g = lane >> 2, t4 = lane & 3;
    uint32_t aAddrBase = smb + SM_A + ((m0 + (lane & 15)) * PAD + (lane >> 4) * 8) * 2;

    // ---- GEMM1: hn = agg @ W1^T ----
    float c[2][4][4];
    #pragma unroll
    for (int mi = 0; mi < 2; mi++)
        #pragma unroll
        for (int ni = 0; ni < 4; ni++)
            #pragma unroll
            for (int q = 0; q < 4; q++) c[mi][ni][q] = 0.f;

    #pragma unroll
    for (int kc = 0; kc < 8; kc++) {
        uint32_t a[2][4];
        ldmatrix4(a[0], aAddrBase + kc * 32);
        ldmatrix4(a[1], aAddrBase + 16 * PAD * 2 + kc * 32);
        #pragma unroll
        for (int ni = 0; ni < 4; ni++) {
            const char* bp = sm + SM_W1 + ((n0 + ni * 8 + g) * PAD + kc * 16 + t4 * 2) * 2;
            uint32_t b0 = *(const uint32_t*)bp;
            uint32_t b1r = *(const uint32_t*)(bp + 16);
            mma16816(c[0][ni], a[0], b0, b1r);
            mma16816(c[1][ni], a[1], b0, b1r);
        }
    }

    // hn = c + bias1 (keep in regs)
    float hn[2][4][4];
    #pragma unroll
    for (int ni = 0; ni < 4; ni++) {
        int col = n0 + ni * 8 + t4 * 2;
        float bb0 = ((const float*)(sm + SM_B1))[col];
        float bb1 = ((const float*)(sm + SM_B1))[col + 1];
        #pragma unroll
        for (int mi = 0; mi < 2; mi++) {
            hn[mi][ni][0] = c[mi][ni][0] + bb0;
            hn[mi][ni][1] = c[mi][ni][1] + bb1;
            hn[mi][ni][2] = c[mi][ni][2] + bb0;
            hn[mi][ni][3] = c[mi][ni][3] + bb1;
        }
    }
    __syncthreads();  // all MMA1 reads of sA done

    // ---- build prod tile (fp16) into sA ----
    #pragma unroll
    for (int mi = 0; mi < 2; mi++) {
        int rlo = m0 + mi * 16 + g, rhi = rlo + 8;
        int glo = row0 + rlo, ghi = row0 + rhi;
        #pragma unroll
        for (int ni = 0; ni < 4; ni++) {
            int col = n0 + ni * 8 + t4 * 2;
            float2 flo = make_float2(0.f, 0.f), fhi = make_float2(0.f, 0.f);
            if (glo < N) flo = *(const float2*)(feat + (size_t)glo * DIM + col);
            if (ghi < N) fhi = *(const float2*)(feat + (size_t)ghi * DIM + col);
            __half2 plo = __floats2half2_rn(flo.x * hn[mi][ni][0], flo.y * hn[mi][ni][1]);
            __half2 phi = __floats2half2_rn(fhi.x * hn[mi][ni][2], fhi.y * hn[mi][ni][3]);
            *(__half2*)(sm + SM_A + (rlo * PAD + col) * 2) = plo;
            *(__half2*)(sm + SM_A + (rhi * PAD + col) * 2) = phi;
        }
    }
    __syncthreads();

    // ---- GEMM2: prod @ W2^T ----
    #pragma unroll
    for (int mi = 0; mi < 2; mi++)
        #pragma unroll
        for (int ni = 0; ni < 4; ni++)
            #pragma unroll
            for (int q = 0; q < 4; q++) c[mi][ni][q] = 0.f;

    #pragma unroll
    for (int kc = 0; kc < 8; kc++) {
        uint32_t a[2][4];
        ldmatrix4(a[0], aAddrBase + kc * 32);
        ldmatrix4(a[1], aAddrBase + 16 * PAD * 2 + kc * 32);
        #pragma unroll
        for (int ni = 0; ni < 4; ni++) {
            const char* bp = sm + SM_W2 + ((n0 + ni * 8 + g) * PAD + kc * 16 + t4 * 2) * 2;
            uint32_t b0 = *(const uint32_t*)bp;
            uint32_t b1r = *(const uint32_t*)(bp + 16);
            mma16816(c[0][ni], a[0], b0, b1r);
            mma16816(c[1][ni], a[1], b0, b1r);
        }
    }

    // ---- epilogue: out = leaky(feat + hn + prod@W2 + b2) ----
    #pragma unroll
    for (int mi = 0; mi < 2; mi++) {
        int rlo = m0 + mi * 16 + g, rhi = rlo + 8;
        int glo = row0 + rlo, ghi = row0 + rhi;
        #pragma unroll
        for (int ni = 0; ni < 4; ni++) {
            int col = n0 + ni * 8 + t4 * 2;
            float bb0 = ((const float*)(sm + SM_B2))[col];
            float bb1 = ((const float*)(sm + SM_B2))[col + 1];
            if (glo < N) {
                float2 f = *(const float2*)(feat + (size_t)glo * DIM + col);
                float2 o;
                o.x = lrelu(c[mi][ni][0] + bb0 + f.x + hn[mi][ni][0]);
                o.y = lrelu(c[mi][ni][1] + bb1 + f.y + hn[mi][ni][1]);
                *(float2*)(out + (size_t)glo * DIM + col) = o;
            }
            if (ghi < N) {
                float2 f = *(const float2*)(feat + (size_t)ghi * DIM + col);
                float2 o;
                o.x = lrelu(c[mi][ni][2] + bb0 + f.x + hn[mi][ni][2]);
                o.y = lrelu(c[mi][ni][3] + bb1 + f.y + hn[mi][ni][3]);
                *(float2*)(out + (size_t)ghi * DIM + col) = o;
            }
        }
    }
}

// ---------------- launch ----------------
extern "C" void kernel_launch(void* const* d_in, const int* in_sizes, int n_in,
                              void* d_out, int out_size) {
    const int*   indices  = (const int*)d_in[0];
    const float* features = (const float*)d_in[1];
    const float* W1_w   = (const float*)d_in[3];
    const float* W1_b   = (const float*)d_in[4];
    const float* W2_w   = (const float*)d_in[5];
    const float* W2_b   = (const float*)d_in[6];
    const float* Watt_w = (const float*)d_in[7];
    const float* Watt_b = (const float*)d_in[8];
    const float* a_vec  = (const float*)d_in[9];

    int E = in_sizes[0] / 2;
    int N = in_sizes[1] / DIM;

    cudaFuncSetAttribute((const void*)k_fused,
                         cudaFuncAttributeMaxDynamicSharedMemorySize, SMEMF);

    float* out = (float*)d_out;

    // slot 1: att vectors + W^T fp16 tables
    k_attw<<<17, 256>>>(Watt_w, Watt_b, a_vec, W1_w, W2_w);
    // slot 2: per-node scores + fp16 feature table
    k_node_scores<<<(N * 32 + 255) / 256, 256>>>(features, N);
    // slot 3: edge buckets
    k_fill<<<(E + 255) / 256, 256>>>(indices, E);
    // slot 4: fused aggregate + double HMMA GEMM + epilogue
    k_fused<<<(N + 127) / 128, 512, SMEMF>>>(features, W1_b, W2_b, out, N);
}

// round 9
// speedup vs baseline: 2.7107x; 1.2420x over previous
#include <cuda_runtime.h>
#include <cuda_fp16.h>
#include <cstdint>

#define DIM 128
#define MAXN 50176
#define SLOTS 128
#define SLOPE 0.2f
#define PAD 136          // halfs per smem row (272B) — conflict-free ldmatrix
typedef unsigned long long u64;

// ---------------- scratch ----------------
__device__ __align__(16) float  g_att[2 * DIM + 8];
__device__ __align__(16) float  g_s1[MAXN];
__device__ __align__(16) float  g_s2[MAXN];
__device__ __align__(16) __half g_featH[(size_t)MAXN * DIM];
__device__ __align__(16) __half g_aggH[(size_t)MAXN * DIM];    // fp16 aggregate
__device__ __align__(16) int    g_counts[MAXN];                // self-zeroing
__device__ __align__(16) u64    g_bucket[(size_t)MAXN * SLOTS];
__device__ __align__(16) __half g_W1T[DIM * PAD];  // W1^T padded: [n][k] = W1[k][n]
__device__ __align__(16) __half g_W2T[DIM * PAD];

__device__ __forceinline__ float lrelu(float x) { return x > 0.f ? x : SLOPE * x; }

__device__ __forceinline__ void mma16816(float* c, const uint32_t* a,
                                         uint32_t b0, uint32_t b1) {
    asm volatile(
        "mma.sync.aligned.m16n8k16.row.col.f32.f16.f16.f32 "
        "{%0,%1,%2,%3}, {%4,%5,%6,%7}, {%8,%9}, {%0,%1,%2,%3};"
        : "+f"(c[0]), "+f"(c[1]), "+f"(c[2]), "+f"(c[3])
        : "r"(a[0]), "r"(a[1]), "r"(a[2]), "r"(a[3]), "r"(b0), "r"(b1));
}
__device__ __forceinline__ void ldmatrix4(uint32_t* a, uint32_t addr) {
    asm volatile("ldmatrix.sync.aligned.m8n8.x4.shared.b16 {%0,%1,%2,%3}, [%4];"
                 : "=r"(a[0]), "=r"(a[1]), "=r"(a[2]), "=r"(a[3]) : "r"(addr));
}

// ---------------- K0: att projection vectors + W^T fp16 tables ----------------
__global__ void k_attw(const float* __restrict__ Watt_w, const float* __restrict__ Watt_b,
                       const float* __restrict__ a,
                       const float* __restrict__ W1_w, const float* __restrict__ W2_w) {
    int tid = threadIdx.x;
    if (blockIdx.x == 0) {
        __shared__ float sc1[DIM], sc2[DIM];
        if (tid < DIM) {
            float v1 = 0.f, v2 = 0.f;
            #pragma unroll 8
            for (int j = 0; j < DIM; j++) {
                float w = Watt_w[tid * DIM + j];
                v1 += w * a[j];
                v2 += w * a[DIM + j];
            }
            g_att[tid] = v1;
            g_att[DIM + tid] = v2;
            sc1[tid] = Watt_b[tid] * a[tid];
            sc2[tid] = Watt_b[tid] * a[DIM + tid];
        }
        __syncthreads();
        for (int s = 64; s > 0; s >>= 1) {
            if (tid < s) { sc1[tid] += sc1[tid + s]; sc2[tid] += sc2[tid + s]; }
            __syncthreads();
        }
        if (tid == 0) { g_att[2 * DIM] = sc1[0]; g_att[2 * DIM + 1] = sc2[0]; }
    } else {
        int base = (blockIdx.x - 1) * 2048 + tid;
        #pragma unroll
        for (int i = 0; i < 8; i++) {
            int e = base + i * 256;
            int wsel = e >> 14;
            int rem = e & 16383;
            int k = rem >> 7, n = rem & 127;
            float v = wsel ? W2_w[rem] : W1_w[rem];
            __half* img = wsel ? g_W2T : g_W1T;
            img[n * PAD + k] = __float2half(v);
        }
    }
}

// ---------------- K1: scores + fp16 feature table ----------------
__global__ void k_node_scores(const float* __restrict__ feat, int N) {
    int warp = (blockIdx.x * blockDim.x + threadIdx.x) >> 5;
    int lane = threadIdx.x & 31;
    if (warp >= N) return;
    float4 f = *(const float4*)(feat + (size_t)warp * DIM + lane * 4);

    __half2 h0 = __floats2half2_rn(f.x, f.y);
    __half2 h1 = __floats2half2_rn(f.z, f.w);
    uint2 raw;
    raw.x = *(unsigned*)&h0;
    raw.y = *(unsigned*)&h1;
    *(uint2*)(g_featH + (size_t)warp * DIM + lane * 4) = raw;

    float4 v1 = *(const float4*)(g_att + lane * 4);
    float4 v2 = *(const float4*)(g_att + DIM + lane * 4);
    float d1 = f.x * v1.x + f.y * v1.y + f.z * v1.z + f.w * v1.w;
    float d2 = f.x * v2.x + f.y * v2.y + f.z * v2.z + f.w * v2.w;
    #pragma unroll
    for (int o = 16; o > 0; o >>= 1) {
        d1 += __shfl_xor_sync(0xffffffffu, d1, o);
        d2 += __shfl_xor_sync(0xffffffffu, d2, o);
    }
    if (lane == 0) {
        g_s1[warp] = d1 + g_att[2 * DIM];
        g_s2[warp] = d2 + g_att[2 * DIM + 1];
    }
}

// ---------------- K2: fill per-dst buckets ----------------
__global__ void k_fill(const int* __restrict__ idx, int E) {
    int e = blockIdx.x * blockDim.x + threadIdx.x;
    if (e >= E) return;
    int s = idx[e];
    int d = idx[E + e];
    float w = __expf(lrelu(g_s1[s] + g_s2[d]));
    int pos = atomicAdd(&g_counts[d], 1);
    pos = min(pos, SLOTS - 1);
    g_bucket[(size_t)d * SLOTS + pos] = ((u64)__float_as_uint(w) << 32) | (unsigned)s;
}

// ---------------- K3 (PROFILED): per-dst aggregation, warp/node, high occ -------
__global__ void __launch_bounds__(256) k_aggregate(int N) {
    int d = (blockIdx.x * blockDim.x + threadIdx.x) >> 5;
    int lane = threadIdx.x & 31;
    if (d >= N) return;
    int cnt = min(g_counts[d], SLOTS);
    const u64* B = g_bucket + (size_t)d * SLOTS;
    const char* featB = (const char*)g_featH + lane * 8;

    float4 acc = make_float4(0.f, 0.f, 0.f, 0.f);
    float wsum = 0.f;
    int j = 0;
    for (; j + 8 <= cnt; j += 8) {
        u64 e[8];
        #pragma unroll
        for (int t = 0; t < 8; t++) e[t] = B[j + t];
        uint2 raw[8];
        #pragma unroll
        for (int t = 0; t < 8; t++)
            raw[t] = *(const uint2*)(featB + ((size_t)(unsigned)e[t] << 8));
        #pragma unroll
        for (int t = 0; t < 8; t++) {
            float w = __uint_as_float((unsigned)(e[t] >> 32));
            float2 a = __half22float2(*(__half2*)&raw[t].x);
            float2 b = __half22float2(*(__half2*)&raw[t].y);
            acc.x += w * a.x; acc.y += w * a.y;
            acc.z += w * b.x; acc.w += w * b.y;
            wsum += w;
        }
    }
    for (; j < cnt; j++) {
        u64 ej = B[j];
        float w = __uint_as_float((unsigned)(ej >> 32));
        uint2 raw = *(const uint2*)(featB + ((size_t)(unsigned)ej << 8));
        float2 a = __half22float2(*(__half2*)&raw.x);
        float2 b = __half22float2(*(__half2*)&raw.y);
        acc.x += w * a.x; acc.y += w * a.y;
        acc.z += w * b.x; acc.w += w * b.y;
        wsum += w;
    }

    if (lane == 0) g_counts[d] = 0;

    float inv = 1.f / (wsum + 1e-9f);
    __half2 p0 = __floats2half2_rn(acc.x * inv, acc.y * inv);
    __half2 p1 = __floats2half2_rn(acc.z * inv, acc.w * inv);
    uint2 pk;
    pk.x = *(unsigned*)&p0;
    pk.y = *(unsigned*)&p1;
    *(uint2*)(g_aggH + (size_t)d * DIM + lane * 4) = pk;
}

// ---------------- K4: fused double HMMA GEMM + epilogue ----------------
static constexpr int SM_B1 = 0;
static constexpr int SM_B2 = 512;
static constexpr int SM_A  = 1024;                 // 128*PAD halfs = 34816B
static constexpr int SM_W1 = SM_A + 128 * PAD * 2;
static constexpr int SM_W2 = SM_W1 + 128 * PAD * 2;
static constexpr int SMEMF = SM_W2 + 128 * PAD * 2;  // 105472B

__global__ void __launch_bounds__(512, 1)
k_gemm(const float* __restrict__ feat,
       const float* __restrict__ b1, const float* __restrict__ b2,
       float* __restrict__ out, int N) {
    extern __shared__ char sm[];
    uint32_t smb;
    asm("{ .reg .u64 t; cvta.to.shared.u64 t, %1; cvt.u32.u64 %0, t; }" : "=r"(smb) : "l"(sm));
    int tid = threadIdx.x, wid = tid >> 5, lane = tid & 31;
    int row0 = blockIdx.x * 128;

    // stage weights + biases + agg tile
    {
        const uint4* w1 = (const uint4*)g_W1T;
        const uint4* w2 = (const uint4*)g_W2T;
        uint4* s1p = (uint4*)(sm + SM_W1);
        uint4* s2p = (uint4*)(sm + SM_W2);
        #pragma unroll 4
        for (int i = tid; i < 128 * PAD / 8; i += 512) { s1p[i] = w1[i]; s2p[i] = w2[i]; }
        if (tid < 128) {
            ((float*)(sm + SM_B1))[tid] = b1[tid];
            ((float*)(sm + SM_B2))[tid] = b2[tid];
        }
        // agg tile: 128 rows x 128 halfs, uint4 = 8 halfs
        #pragma unroll
        for (int i = tid; i < 128 * 16; i += 512) {
            int r = i >> 4, c8 = (i & 15) << 3;
            int gr = row0 + r;
            uint4 v = make_uint4(0u, 0u, 0u, 0u);
            if (gr < N) v = *(const uint4*)(g_aggH + (size_t)gr * DIM + c8);
            *(uint4*)(sm + SM_A + (r * PAD + c8) * 2) = v;
        }
    }
    __syncthreads();

    // warp grid 4x4: 32x32 output tile per warp
    int m0 = (wid >> 2) * 32, n0 = (wid & 3) * 32;
    int g = lane >> 2, t4 = lane & 3;
    uint32_t aAddrBase = smb + SM_A + ((m0 + (lane & 15)) * PAD + (lane >> 4) * 8) * 2;

    // ---- GEMM1: hn = agg @ W1^T ----
    float c[2][4][4];
    #pragma unroll
    for (int mi = 0; mi < 2; mi++)
        #pragma unroll
        for (int ni = 0; ni < 4; ni++)
            #pragma unroll
            for (int q = 0; q < 4; q++) c[mi][ni][q] = 0.f;

    #pragma unroll
    for (int kc = 0; kc < 8; kc++) {
        uint32_t a[2][4];
        ldmatrix4(a[0], aAddrBase + kc * 32);
        ldmatrix4(a[1], aAddrBase + 16 * PAD * 2 + kc * 32);
        #pragma unroll
        for (int ni = 0; ni < 4; ni++) {
            const char* bp = sm + SM_W1 + ((n0 + ni * 8 + g) * PAD + kc * 16 + t4 * 2) * 2;
            uint32_t b0 = *(const uint32_t*)bp;
            uint32_t b1r = *(const uint32_t*)(bp + 16);
            mma16816(c[0][ni], a[0], b0, b1r);
            mma16816(c[1][ni], a[1], b0, b1r);
        }
    }

    float hn[2][4][4];
    #pragma unroll
    for (int ni = 0; ni < 4; ni++) {
        int col = n0 + ni * 8 + t4 * 2;
        float bb0 = ((const float*)(sm + SM_B1))[col];
        float bb1 = ((const float*)(sm + SM_B1))[col + 1];
        #pragma unroll
        for (int mi = 0; mi < 2; mi++) {
            hn[mi][ni][0] = c[mi][ni][0] + bb0;
            hn[mi][ni][1] = c[mi][ni][1] + bb1;
            hn[mi][ni][2] = c[mi][ni][2] + bb0;
            hn[mi][ni][3] = c[mi][ni][3] + bb1;
        }
    }
    __syncthreads();

    // ---- build prod tile (fp16) into sA ----
    #pragma unroll
    for (int mi = 0; mi < 2; mi++) {
        int rlo = m0 + mi * 16 + g, rhi = rlo + 8;
        int glo = row0 + rlo, ghi = row0 + rhi;
        #pragma unroll
        for (int ni = 0; ni < 4; ni++) {
            int col = n0 + ni * 8 + t4 * 2;
            float2 flo = make_float2(0.f, 0.f), fhi = make_float2(0.f, 0.f);
            if (glo < N) flo = *(const float2*)(feat + (size_t)glo * DIM + col);
            if (ghi < N) fhi = *(const float2*)(feat + (size_t)ghi * DIM + col);
            __half2 plo = __floats2half2_rn(flo.x * hn[mi][ni][0], flo.y * hn[mi][ni][1]);
            __half2 phi = __floats2half2_rn(fhi.x * hn[mi][ni][2], fhi.y * hn[mi][ni][3]);
            *(__half2*)(sm + SM_A + (rlo * PAD + col) * 2) = plo;
            *(__half2*)(sm + SM_A + (rhi * PAD + col) * 2) = phi;
        }
    }
    __syncthreads();

    // ---- GEMM2: prod @ W2^T ----
    #pragma unroll
    for (int mi = 0; mi < 2; mi++)
        #pragma unroll
        for (int ni = 0; ni < 4; ni++)
            #pragma unroll
            for (int q = 0; q < 4; q++) c[mi][ni][q] = 0.f;

    #pragma unroll
    for (int kc = 0; kc < 8; kc++) {
        uint32_t a[2][4];
        ldmatrix4(a[0], aAddrBase + kc * 32);
        ldmatrix4(a[1], aAddrBase + 16 * PAD * 2 + kc * 32);
        #pragma unroll
        for (int ni = 0; ni < 4; ni++) {
            const char* bp = sm + SM_W2 + ((n0 + ni * 8 + g) * PAD + kc * 16 + t4 * 2) * 2;
            uint32_t b0 = *(const uint32_t*)bp;
            uint32_t b1r = *(const uint32_t*)(bp + 16);
            mma16816(c[0][ni], a[0], b0, b1r);
            mma16816(c[1][ni], a[1], b0, b1r);
        }
    }

    // ---- epilogue: out = leaky(feat + hn + prod@W2 + b2) ----
    #pragma unroll
    for (int mi = 0; mi < 2; mi++) {
        int rlo = m0 + mi * 16 + g, rhi = rlo + 8;
        int glo = row0 + rlo, ghi = row0 + rhi;
        #pragma unroll
        for (int ni = 0; ni < 4; ni++) {
            int col = n0 + ni * 8 + t4 * 2;
            float bb0 = ((const float*)(sm + SM_B2))[col];
            float bb1 = ((const float*)(sm + SM_B2))[col + 1];
            if (glo < N) {
                float2 f = *(const float2*)(feat + (size_t)glo * DIM + col);
                float2 o;
                o.x = lrelu(c[mi][ni][0] + bb0 + f.x + hn[mi][ni][0]);
                o.y = lrelu(c[mi][ni][1] + bb1 + f.y + hn[mi][ni][1]);
                *(float2*)(out + (size_t)glo * DIM + col) = o;
            }
            if (ghi < N) {
                float2 f = *(const float2*)(feat + (size_t)ghi * DIM + col);
                float2 o;
                o.x = lrelu(c[mi][ni][2] + bb0 + f.x + hn[mi][ni][2]);
                o.y = lrelu(c[mi][ni][3] + bb1 + f.y + hn[mi][ni][3]);
                *(float2*)(out + (size_t)ghi * DIM + col) = o;
            }
        }
    }
}

// ---------------- launch ----------------
extern "C" void kernel_launch(void* const* d_in, const int* in_sizes, int n_in,
                              void* d_out, int out_size) {
    const int*   indices  = (const int*)d_in[0];
    const float* features = (const float*)d_in[1];
    const float* W1_w   = (const float*)d_in[3];
    const float* W1_b   = (const float*)d_in[4];
    const float* W2_w   = (const float*)d_in[5];
    const float* W2_b   = (const float*)d_in[6];
    const float* Watt_w = (const float*)d_in[7];
    const float* Watt_b = (const float*)d_in[8];
    const float* a_vec  = (const float*)d_in[9];

    int E = in_sizes[0] / 2;
    int N = in_sizes[1] / DIM;

    cudaFuncSetAttribute((const void*)k_gemm,
                         cudaFuncAttributeMaxDynamicSharedMemorySize, SMEMF);

    float* out = (float*)d_out;

    // slot 1: att vectors + W^T fp16 tables
    k_attw<<<17, 256>>>(Watt_w, Watt_b, a_vec, W1_w, W2_w);
    // slot 2: per-node scores + fp16 feature table
    k_node_scores<<<(N * 32 + 255) / 256, 256>>>(features, N);
    // slot 3: edge buckets
    k_fill<<<(E + 255) / 256, 256>>>(indices, E);
    // slot 4 (profiled): aggregation at high occupancy
    k_aggregate<<<(N * 32 + 255) / 256, 256>>>(N);
    // slot 5: fused double HMMA GEMM + epilogue
    k_gemm<<<(N + 127) / 128, 512, SMEMF>>>(features, W1_b, W2_b, out, N);
}

// round 10
// speedup vs baseline: 2.9620x; 1.0927x over previous
#include <cuda_runtime.h>
#include <cuda_fp16.h>
#include <cstdint>

#define DIM 128
#define MAXN 50176
#define SLOTS 128
#define SLOPE 0.2f
#define PAD 136          // halfs per smem row (272B) — conflict-free ldmatrix
typedef unsigned long long u64;

// ---------------- scratch ----------------
__device__ __align__(16) float  g_att[2 * DIM + 8];
__device__ __align__(16) float  g_s1[MAXN];
__device__ __align__(16) float  g_s2[MAXN];
__device__ __align__(16) __half g_featH[(size_t)MAXN * DIM];
__device__ __align__(16) __half g_aggH[(size_t)MAXN * DIM];     // fp16 aggregate
__device__ __align__(16) int    g_counts[MAXN];                 // self-zeroing
__device__ __align__(16) unsigned g_bucket[(size_t)MAXN * SLOTS]; // (halfW<<16)|src
__device__ __align__(16) __half g_W1T[DIM * PAD];  // W1^T padded: [n][k] = W1[k][n]
__device__ __align__(16) __half g_W2T[DIM * PAD];

__device__ __forceinline__ float lrelu(float x) { return x > 0.f ? x : SLOPE * x; }

__device__ __forceinline__ void mma16816(float* c, const uint32_t* a,
                                         uint32_t b0, uint32_t b1) {
    asm volatile(
        "mma.sync.aligned.m16n8k16.row.col.f32.f16.f16.f32 "
        "{%0,%1,%2,%3}, {%4,%5,%6,%7}, {%8,%9}, {%0,%1,%2,%3};"
        : "+f"(c[0]), "+f"(c[1]), "+f"(c[2]), "+f"(c[3])
        : "r"(a[0]), "r"(a[1]), "r"(a[2]), "r"(a[3]), "r"(b0), "r"(b1));
}
__device__ __forceinline__ void ldmatrix4(uint32_t* a, uint32_t addr) {
    asm volatile("ldmatrix.sync.aligned.m8n8.x4.shared.b16 {%0,%1,%2,%3}, [%4];"
                 : "=r"(a[0]), "=r"(a[1]), "=r"(a[2]), "=r"(a[3]) : "r"(addr));
}

// ---------------- K0: att projection vectors + W^T fp16 tables ----------------
__global__ void k_attw(const float* __restrict__ Watt_w, const float* __restrict__ Watt_b,
                       const float* __restrict__ a,
                       const float* __restrict__ W1_w, const float* __restrict__ W2_w) {
    int tid = threadIdx.x;
    if (blockIdx.x == 0) {
        __shared__ float sc1[DIM], sc2[DIM];
        if (tid < DIM) {
            float v1 = 0.f, v2 = 0.f;
            #pragma unroll 8
            for (int j = 0; j < DIM; j++) {
                float w = Watt_w[tid * DIM + j];
                v1 += w * a[j];
                v2 += w * a[DIM + j];
            }
            g_att[tid] = v1;
            g_att[DIM + tid] = v2;
            sc1[tid] = Watt_b[tid] * a[tid];
            sc2[tid] = Watt_b[tid] * a[DIM + tid];
        }
        __syncthreads();
        for (int s = 64; s > 0; s >>= 1) {
            if (tid < s) { sc1[tid] += sc1[tid + s]; sc2[tid] += sc2[tid + s]; }
            __syncthreads();
        }
        if (tid == 0) { g_att[2 * DIM] = sc1[0]; g_att[2 * DIM + 1] = sc2[0]; }
    } else {
        int base = (blockIdx.x - 1) * 2048 + tid;
        #pragma unroll
        for (int i = 0; i < 8; i++) {
            int e = base + i * 256;
            int wsel = e >> 14;
            int rem = e & 16383;
            int k = rem >> 7, n = rem & 127;
            float v = wsel ? W2_w[rem] : W1_w[rem];
            __half* img = wsel ? g_W2T : g_W1T;
            img[n * PAD + k] = __float2half(v);
        }
    }
}

// ---------------- K1: scores + fp16 feature table ----------------
__global__ void k_node_scores(const float* __restrict__ feat, int N) {
    int warp = (blockIdx.x * blockDim.x + threadIdx.x) >> 5;
    int lane = threadIdx.x & 31;
    if (warp >= N) return;
    float4 f = *(const float4*)(feat + (size_t)warp * DIM + lane * 4);

    __half2 h0 = __floats2half2_rn(f.x, f.y);
    __half2 h1 = __floats2half2_rn(f.z, f.w);
    uint2 raw;
    raw.x = *(unsigned*)&h0;
    raw.y = *(unsigned*)&h1;
    *(uint2*)(g_featH + (size_t)warp * DIM + lane * 4) = raw;

    float4 v1 = *(const float4*)(g_att + lane * 4);
    float4 v2 = *(const float4*)(g_att + DIM + lane * 4);
    float d1 = f.x * v1.x + f.y * v1.y + f.z * v1.z + f.w * v1.w;
    float d2 = f.x * v2.x + f.y * v2.y + f.z * v2.z + f.w * v2.w;
    #pragma unroll
    for (int o = 16; o > 0; o >>= 1) {
        d1 += __shfl_xor_sync(0xffffffffu, d1, o);
        d2 += __shfl_xor_sync(0xffffffffu, d2, o);
    }
    if (lane == 0) {
        g_s1[warp] = d1 + g_att[2 * DIM];
        g_s2[warp] = d2 + g_att[2 * DIM + 1];
    }
}

// ---------------- K2: fill per-dst buckets (packed u32: halfW<<16 | src) ---------
__global__ void k_fill(const int* __restrict__ idx, int E) {
    int e = blockIdx.x * blockDim.x + threadIdx.x;
    if (e >= E) return;
    int s = idx[e];
    int d = idx[E + e];
    float w = __expf(lrelu(g_s1[s] + g_s2[d]));
    unsigned hw = (unsigned)__half_as_ushort(__float2half_rn(w));
    int pos = atomicAdd(&g_counts[d], 1);
    pos = min(pos, SLOTS - 1);
    g_bucket[(size_t)d * SLOTS + pos] = (hw << 16) | (unsigned)s;
}

// ---------------- K3 (PROFILED): aggregation, HFMA2 accum, u32 buckets ----------
__global__ void __launch_bounds__(256) k_aggregate(int N) {
    int d = (blockIdx.x * blockDim.x + threadIdx.x) >> 5;
    int lane = threadIdx.x & 31;
    if (d >= N) return;
    int cnt = min(g_counts[d], SLOTS);
    const uint4* B4 = (const uint4*)(g_bucket + (size_t)d * SLOTS);
    const char* featB = (const char*)g_featH + lane * 8;

    __half2 acc01 = __float2half2_rn(0.f);
    __half2 acc23 = __float2half2_rn(0.f);
    float wsum = 0.f;

    int j = 0;
    for (; j + 8 <= cnt; j += 8) {
        uint4 q0 = B4[(j >> 2) + 0];
        uint4 q1 = B4[(j >> 2) + 1];
        unsigned e[8] = {q0.x, q0.y, q0.z, q0.w, q1.x, q1.y, q1.z, q1.w};
        uint2 raw[8];
        #pragma unroll
        for (int t = 0; t < 8; t++)
            raw[t] = *(const uint2*)(featB + ((size_t)(e[t] & 0xFFFFu) << 8));
        #pragma unroll
        for (int t = 0; t < 8; t++) {
            unsigned w2u = __byte_perm(e[t], e[t], 0x3232);  // half2(w, w)
            __half2 w2 = *(__half2*)&w2u;
            acc01 = __hfma2(w2, *(__half2*)&raw[t].x, acc01);
            acc23 = __hfma2(w2, *(__half2*)&raw[t].y, acc23);
            wsum += __half2float(__ushort_as_half((unsigned short)(e[t] >> 16)));
        }
    }
    for (; j < cnt; j++) {
        unsigned e = g_bucket[(size_t)d * SLOTS + j];
        uint2 raw = *(const uint2*)(featB + ((size_t)(e & 0xFFFFu) << 8));
        unsigned w2u = __byte_perm(e, e, 0x3232);
        __half2 w2 = *(__half2*)&w2u;
        acc01 = __hfma2(w2, *(__half2*)&raw.x, acc01);
        acc23 = __hfma2(w2, *(__half2*)&raw.y, acc23);
        wsum += __half2float(__ushort_as_half((unsigned short)(e >> 16)));
    }

    if (lane == 0) g_counts[d] = 0;

    float inv = 1.f / (wsum + 1e-9f);
    float2 a01 = __half22float2(acc01);
    float2 a23 = __half22float2(acc23);
    __half2 p0 = __floats2half2_rn(a01.x * inv, a01.y * inv);
    __half2 p1 = __floats2half2_rn(a23.x * inv, a23.y * inv);
    uint2 pk;
    pk.x = *(unsigned*)&p0;
    pk.y = *(unsigned*)&p1;
    *(uint2*)(g_aggH + (size_t)d * DIM + lane * 4) = pk;
}

// ---------------- K4: fused double HMMA GEMM + epilogue ----------------
static constexpr int SM_B1 = 0;
static constexpr int SM_B2 = 512;
static constexpr int SM_A  = 1024;                 // 128*PAD halfs = 34816B
static constexpr int SM_W1 = SM_A + 128 * PAD * 2;
static constexpr int SM_W2 = SM_W1 + 128 * PAD * 2;
static constexpr int SMEMF = SM_W2 + 128 * PAD * 2;  // 105472B

__global__ void __launch_bounds__(512, 1)
k_gemm(const float* __restrict__ feat,
       const float* __restrict__ b1, const float* __restrict__ b2,
       float* __restrict__ out, int N) {
    extern __shared__ char sm[];
    uint32_t smb;
    asm("{ .reg .u64 t; cvta.to.shared.u64 t, %1; cvt.u32.u64 %0, t; }" : "=r"(smb) : "l"(sm));
    int tid = threadIdx.x, wid = tid >> 5, lane = tid & 31;
    int row0 = blockIdx.x * 128;

    {
        const uint4* w1 = (const uint4*)g_W1T;
        const uint4* w2 = (const uint4*)g_W2T;
        uint4* s1p = (uint4*)(sm + SM_W1);
        uint4* s2p = (uint4*)(sm + SM_W2);
        #pragma unroll 4
        for (int i = tid; i < 128 * PAD / 8; i += 512) { s1p[i] = w1[i]; s2p[i] = w2[i]; }
        if (tid < 128) {
            ((float*)(sm + SM_B1))[tid] = b1[tid];
            ((float*)(sm + SM_B2))[tid] = b2[tid];
        }
        #pragma unroll
        for (int i = tid; i < 128 * 16; i += 512) {
            int r = i >> 4, c8 = (i & 15) << 3;
            int gr = row0 + r;
            uint4 v = make_uint4(0u, 0u, 0u, 0u);
            if (gr < N) v = *(const uint4*)(g_aggH + (size_t)gr * DIM + c8);
            *(uint4*)(sm + SM_A + (r * PAD + c8) * 2) = v;
        }
    }
    __syncthreads();

    int m0 = (wid >> 2) * 32, n0 = (wid & 3) * 32;
    int g = lane >> 2, t4 = lane & 3;
    uint32_t aAddrBase = smb + SM_A + ((m0 + (lane & 15)) * PAD + (lane >> 4) * 8) * 2;

    // ---- GEMM1 ----
    float c[2][4][4];
    #pragma unroll
    for (int mi = 0; mi < 2; mi++)
        #pragma unroll
        for (int ni = 0; ni < 4; ni++)
            #pragma unroll
            for (int q = 0; q < 4; q++) c[mi][ni][q] = 0.f;

    #pragma unroll
    for (int kc = 0; kc < 8; kc++) {
        uint32_t a[2][4];
        ldmatrix4(a[0], aAddrBase + kc * 32);
        ldmatrix4(a[1], aAddrBase + 16 * PAD * 2 + kc * 32);
        #pragma unroll
        for (int ni = 0; ni < 4; ni++) {
            const char* bp = sm + SM_W1 + ((n0 + ni * 8 + g) * PAD + kc * 16 + t4 * 2) * 2;
            uint32_t b0 = *(const uint32_t*)bp;
            uint32_t b1r = *(const uint32_t*)(bp + 16);
            mma16816(c[0][ni], a[0], b0, b1r);
            mma16816(c[1][ni], a[1], b0, b1r);
        }
    }

    float hn[2][4][4];
    #pragma unroll
    for (int ni = 0; ni < 4; ni++) {
        int col = n0 + ni * 8 + t4 * 2;
        float bb0 = ((const float*)(sm + SM_B1))[col];
        float bb1 = ((const float*)(sm + SM_B1))[col + 1];
        #pragma unroll
        for (int mi = 0; mi < 2; mi++) {
            hn[mi][ni][0] = c[mi][ni][0] + bb0;
            hn[mi][ni][1] = c[mi][ni][1] + bb1;
            hn[mi][ni][2] = c[mi][ni][2] + bb0;
            hn[mi][ni][3] = c[mi][ni][3] + bb1;
        }
    }
    __syncthreads();

    // ---- prod tile ----
    #pragma unroll
    for (int mi = 0; mi < 2; mi++) {
        int rlo = m0 + mi * 16 + g, rhi = rlo + 8;
        int glo = row0 + rlo, ghi = row0 + rhi;
        #pragma unroll
        for (int ni = 0; ni < 4; ni++) {
            int col = n0 + ni * 8 + t4 * 2;
            float2 flo = make_float2(0.f, 0.f), fhi = make_float2(0.f, 0.f);
            if (glo < N) flo = *(const float2*)(feat + (size_t)glo * DIM + col);
            if (ghi < N) fhi = *(const float2*)(feat + (size_t)ghi * DIM + col);
            __half2 plo = __floats2half2_rn(flo.x * hn[mi][ni][0], flo.y * hn[mi][ni][1]);
            __half2 phi = __floats2half2_rn(fhi.x * hn[mi][ni][2], fhi.y * hn[mi][ni][3]);
            *(__half2*)(sm + SM_A + (rlo * PAD + col) * 2) = plo;
            *(__half2*)(sm + SM_A + (rhi * PAD + col) * 2) = phi;
        }
    }
    __syncthreads();

    // ---- GEMM2 ----
    #pragma unroll
    for (int mi = 0; mi < 2; mi++)
        #pragma unroll
        for (int ni = 0; ni < 4; ni++)
            #pragma unroll
            for (int q = 0; q < 4; q++) c[mi][ni][q] = 0.f;

    #pragma unroll
    for (int kc = 0; kc < 8; kc++) {
        uint32_t a[2][4];
        ldmatrix4(a[0], aAddrBase + kc * 32);
        ldmatrix4(a[1], aAddrBase + 16 * PAD * 2 + kc * 32);
        #pragma unroll
        for (int ni = 0; ni < 4; ni++) {
            const char* bp = sm + SM_W2 + ((n0 + ni * 8 + g) * PAD + kc * 16 + t4 * 2) * 2;
            uint32_t b0 = *(const uint32_t*)bp;
            uint32_t b1r = *(const uint32_t*)(bp + 16);
            mma16816(c[0][ni], a[0], b0, b1r);
            mma16816(c[1][ni], a[1], b0, b1r);
        }
    }

    // ---- epilogue ----
    #pragma unroll
    for (int mi = 0; mi < 2; mi++) {
        int rlo = m0 + mi * 16 + g, rhi = rlo + 8;
        int glo = row0 + rlo, ghi = row0 + rhi;
        #pragma unroll
        for (int ni = 0; ni < 4; ni++) {
            int col = n0 + ni * 8 + t4 * 2;
            float bb0 = ((const float*)(sm + SM_B2))[col];
            float bb1 = ((const float*)(sm + SM_B2))[col + 1];
            if (glo < N) {
                float2 f = *(const float2*)(feat + (size_t)glo * DIM + col);
                float2 o;
                o.x = lrelu(c[mi][ni][0] + bb0 + f.x + hn[mi][ni][0]);
                o.y = lrelu(c[mi][ni][1] + bb1 + f.y + hn[mi][ni][1]);
                *(float2*)(out + (size_t)glo * DIM + col) = o;
            }
            if (ghi < N) {
                float2 f = *(const float2*)(feat + (size_t)ghi * DIM + col);
                float2 o;
                o.x = lrelu(c[mi][ni][2] + bb0 + f.x + hn[mi][ni][2]);
                o.y = lrelu(c[mi][ni][3] + bb1 + f.y + hn[mi][ni][3]);
                *(float2*)(out + (size_t)ghi * DIM + col) = o;
            }
        }
    }
}

// ---------------- launch ----------------
extern "C" void kernel_launch(void* const* d_in, const int* in_sizes, int n_in,
                              void* d_out, int out_size) {
    const int*   indices  = (const int*)d_in[0];
    const float* features = (const float*)d_in[1];
    const float* W1_w   = (const float*)d_in[3];
    const float* W1_b   = (const float*)d_in[4];
    const float* W2_w   = (const float*)d_in[5];
    const float* W2_b   = (const float*)d_in[6];
    const float* Watt_w = (const float*)d_in[7];
    const float* Watt_b = (const float*)d_in[8];
    const float* a_vec  = (const float*)d_in[9];

    int E = in_sizes[0] / 2;
    int N = in_sizes[1] / DIM;

    cudaFuncSetAttribute((const void*)k_gemm,
                         cudaFuncAttributeMaxDynamicSharedMemorySize, SMEMF);

    float* out = (float*)d_out;

    // slot 1
    k_attw<<<17, 256>>>(Watt_w, Watt_b, a_vec, W1_w, W2_w);
    // slot 2
    k_node_scores<<<(N * 32 + 255) / 256, 256>>>(features, N);
    // slot 3
    k_fill<<<(E + 255) / 256, 256>>>(indices, E);
    // slot 4 (profiled)
    k_aggregate<<<(N * 32 + 255) / 256, 256>>>(N);
    // slot 5
    k_gemm<<<(N + 127) / 128, 512, SMEMF>>>(features, W1_b, W2_b, out, N);
}

// round 11
// speedup vs baseline: 2.9926x; 1.0103x over previous
#include <cuda_runtime.h>
#include <cuda_fp16.h>
#include <cstdint>

#define DIM 128
#define MAXN 50176
#define SLOTS 128
#define SLOPE 0.2f
#define PAD 136          // halfs per smem row (272B) — conflict-free ldmatrix
typedef unsigned long long u64;

// ---------------- scratch ----------------
__device__ __align__(16) float  g_att[2 * DIM + 8];
__device__ __align__(16) float  g_s1[MAXN];
__device__ __align__(16) float  g_s2[MAXN];
__device__ __align__(16) __half g_featH[(size_t)MAXN * DIM];
__device__ __align__(16) __half g_aggH[(size_t)MAXN * DIM];     // fp16 aggregate
__device__ __align__(16) int    g_counts[MAXN];                 // self-zeroing
__device__ __align__(16) unsigned g_bucket[(size_t)MAXN * SLOTS]; // (halfW<<16)|src
__device__ __align__(16) __half g_W1T[DIM * PAD];  // W1^T padded: [n][k] = W1[k][n]
__device__ __align__(16) __half g_W2T[DIM * PAD];

__device__ __forceinline__ float lrelu(float x) { return x > 0.f ? x : SLOPE * x; }

__device__ __forceinline__ void mma16816(float* c, const uint32_t* a,
                                         uint32_t b0, uint32_t b1) {
    asm volatile(
        "mma.sync.aligned.m16n8k16.row.col.f32.f16.f16.f32 "
        "{%0,%1,%2,%3}, {%4,%5,%6,%7}, {%8,%9}, {%0,%1,%2,%3};"
        : "+f"(c[0]), "+f"(c[1]), "+f"(c[2]), "+f"(c[3])
        : "r"(a[0]), "r"(a[1]), "r"(a[2]), "r"(a[3]), "r"(b0), "r"(b1));
}
__device__ __forceinline__ void ldmatrix4(uint32_t* a, uint32_t addr) {
    asm volatile("ldmatrix.sync.aligned.m8n8.x4.shared.b16 {%0,%1,%2,%3}, [%4];"
                 : "=r"(a[0]), "=r"(a[1]), "=r"(a[2]), "=r"(a[3]) : "r"(addr));
}

// ---------------- K0: att projection vectors + W^T fp16 tables ----------------
__global__ void k_attw(const float* __restrict__ Watt_w, const float* __restrict__ Watt_b,
                       const float* __restrict__ a,
                       const float* __restrict__ W1_w, const float* __restrict__ W2_w) {
    int tid = threadIdx.x;
    if (blockIdx.x == 0) {
        __shared__ float sc1[DIM], sc2[DIM];
        if (tid < DIM) {
            float v1 = 0.f, v2 = 0.f;
            #pragma unroll 8
            for (int j = 0; j < DIM; j++) {
                float w = Watt_w[tid * DIM + j];
                v1 += w * a[j];
                v2 += w * a[DIM + j];
            }
            g_att[tid] = v1;
            g_att[DIM + tid] = v2;
            sc1[tid] = Watt_b[tid] * a[tid];
            sc2[tid] = Watt_b[tid] * a[DIM + tid];
        }
        __syncthreads();
        for (int s = 64; s > 0; s >>= 1) {
            if (tid < s) { sc1[tid] += sc1[tid + s]; sc2[tid] += sc2[tid + s]; }
            __syncthreads();
        }
        if (tid == 0) { g_att[2 * DIM] = sc1[0]; g_att[2 * DIM + 1] = sc2[0]; }
    } else {
        int base = (blockIdx.x - 1) * 2048 + tid;
        #pragma unroll
        for (int i = 0; i < 8; i++) {
            int e = base + i * 256;
            int wsel = e >> 14;
            int rem = e & 16383;
            int k = rem >> 7, n = rem & 127;
            float v = wsel ? W2_w[rem] : W1_w[rem];
            __half* img = wsel ? g_W2T : g_W1T;
            img[n * PAD + k] = __float2half(v);
        }
    }
}

// ---------------- K1: scores + fp16 feature table ----------------
__global__ void k_node_scores(const float* __restrict__ feat, int N) {
    int warp = (blockIdx.x * blockDim.x + threadIdx.x) >> 5;
    int lane = threadIdx.x & 31;
    if (warp >= N) return;
    float4 f = *(const float4*)(feat + (size_t)warp * DIM + lane * 4);

    __half2 h0 = __floats2half2_rn(f.x, f.y);
    __half2 h1 = __floats2half2_rn(f.z, f.w);
    uint2 raw;
    raw.x = *(unsigned*)&h0;
    raw.y = *(unsigned*)&h1;
    *(uint2*)(g_featH + (size_t)warp * DIM + lane * 4) = raw;

    float4 v1 = *(const float4*)(g_att + lane * 4);
    float4 v2 = *(const float4*)(g_att + DIM + lane * 4);
    float d1 = f.x * v1.x + f.y * v1.y + f.z * v1.z + f.w * v1.w;
    float d2 = f.x * v2.x + f.y * v2.y + f.z * v2.z + f.w * v2.w;
    #pragma unroll
    for (int o = 16; o > 0; o >>= 1) {
        d1 += __shfl_xor_sync(0xffffffffu, d1, o);
        d2 += __shfl_xor_sync(0xffffffffu, d2, o);
    }
    if (lane == 0) {
        g_s1[warp] = d1 + g_att[2 * DIM];
        g_s2[warp] = d2 + g_att[2 * DIM + 1];
    }
}

// ---------------- K2: fill per-dst buckets (packed u32: halfW<<16 | src) ---------
__global__ void k_fill(const int* __restrict__ idx, int E) {
    int e = blockIdx.x * blockDim.x + threadIdx.x;
    if (e >= E) return;
    int s = idx[e];
    int d = idx[E + e];
    float w = __expf(lrelu(g_s1[s] + g_s2[d]));
    unsigned hw = (unsigned)__half_as_ushort(__float2half_rn(w));
    int pos = atomicAdd(&g_counts[d], 1);
    pos = min(pos, SLOTS - 1);
    g_bucket[(size_t)d * SLOTS + pos] = (hw << 16) | (unsigned)s;
}

// ---------------- K3 (PROFILED): aggregation; wsum via coalesced pre-pass --------
__global__ void __launch_bounds__(256) k_aggregate(int N) {
    int d = (blockIdx.x * blockDim.x + threadIdx.x) >> 5;
    int lane = threadIdx.x & 31;
    if (d >= N) return;
    int cnt = min(g_counts[d], SLOTS);
    const unsigned* B = g_bucket + (size_t)d * SLOTS;
    const uint4* B4 = (const uint4*)B;
    const char* featB = (const char*)g_featH + lane * 8;

    // wsum: one coalesced strided pass + warp reduction (replaces per-edge F2F+FADD)
    float wsum = 0.f;
    for (int j = lane; j < cnt; j += 32)
        wsum += __half2float(__ushort_as_half((unsigned short)(B[j] >> 16)));
    #pragma unroll
    for (int o = 16; o > 0; o >>= 1)
        wsum += __shfl_xor_sync(0xffffffffu, wsum, o);

    __half2 acc01 = __float2half2_rn(0.f);
    __half2 acc23 = __float2half2_rn(0.f);

    int j = 0;
    for (; j + 8 <= cnt; j += 8) {
        uint4 q0 = B4[(j >> 2) + 0];
        uint4 q1 = B4[(j >> 2) + 1];
        unsigned e[8] = {q0.x, q0.y, q0.z, q0.w, q1.x, q1.y, q1.z, q1.w};
        uint2 raw[8];
        #pragma unroll
        for (int t = 0; t < 8; t++)
            raw[t] = *(const uint2*)(featB + ((size_t)(e[t] & 0xFFFFu) << 8));
        #pragma unroll
        for (int t = 0; t < 8; t++) {
            unsigned w2u = __byte_perm(e[t], e[t], 0x3232);  // half2(w, w)
            __half2 w2 = *(__half2*)&w2u;
            acc01 = __hfma2(w2, *(__half2*)&raw[t].x, acc01);
            acc23 = __hfma2(w2, *(__half2*)&raw[t].y, acc23);
        }
    }
    for (; j < cnt; j++) {
        unsigned e = B[j];
        uint2 raw = *(const uint2*)(featB + ((size_t)(e & 0xFFFFu) << 8));
        unsigned w2u = __byte_perm(e, e, 0x3232);
        __half2 w2 = *(__half2*)&w2u;
        acc01 = __hfma2(w2, *(__half2*)&raw.x, acc01);
        acc23 = __hfma2(w2, *(__half2*)&raw.y, acc23);
    }

    if (lane == 0) g_counts[d] = 0;

    float inv = 1.f / (wsum + 1e-9f);
    float2 a01 = __half22float2(acc01);
    float2 a23 = __half22float2(acc23);
    __half2 p0 = __floats2half2_rn(a01.x * inv, a01.y * inv);
    __half2 p1 = __floats2half2_rn(a23.x * inv, a23.y * inv);
    uint2 pk;
    pk.x = *(unsigned*)&p0;
    pk.y = *(unsigned*)&p1;
    *(uint2*)(g_aggH + (size_t)d * DIM + lane * 4) = pk;
}

// ---------------- K4: fused double HMMA GEMM + epilogue ----------------
static constexpr int SM_B1 = 0;
static constexpr int SM_B2 = 512;
static constexpr int SM_A  = 1024;                 // 128*PAD halfs = 34816B
static constexpr int SM_W1 = SM_A + 128 * PAD * 2;
static constexpr int SM_W2 = SM_W1 + 128 * PAD * 2;
static constexpr int SMEMF = SM_W2 + 128 * PAD * 2;  // 105472B

__global__ void __launch_bounds__(512, 1)
k_gemm(const float* __restrict__ feat,
       const float* __restrict__ b1, const float* __restrict__ b2,
       float* __restrict__ out, int N) {
    extern __shared__ char sm[];
    uint32_t smb;
    asm("{ .reg .u64 t; cvta.to.shared.u64 t, %1; cvt.u32.u64 %0, t; }" : "=r"(smb) : "l"(sm));
    int tid = threadIdx.x, wid = tid >> 5, lane = tid & 31;
    int row0 = blockIdx.x * 128;

    {
        const uint4* w1 = (const uint4*)g_W1T;
        const uint4* w2 = (const uint4*)g_W2T;
        uint4* s1p = (uint4*)(sm + SM_W1);
        uint4* s2p = (uint4*)(sm + SM_W2);
        #pragma unroll 4
        for (int i = tid; i < 128 * PAD / 8; i += 512) { s1p[i] = w1[i]; s2p[i] = w2[i]; }
        if (tid < 128) {
            ((float*)(sm + SM_B1))[tid] = b1[tid];
            ((float*)(sm + SM_B2))[tid] = b2[tid];
        }
        #pragma unroll
        for (int i = tid; i < 128 * 16; i += 512) {
            int r = i >> 4, c8 = (i & 15) << 3;
            int gr = row0 + r;
            uint4 v = make_uint4(0u, 0u, 0u, 0u);
            if (gr < N) v = *(const uint4*)(g_aggH + (size_t)gr * DIM + c8);
            *(uint4*)(sm + SM_A + (r * PAD + c8) * 2) = v;
        }
    }
    __syncthreads();

    int m0 = (wid >> 2) * 32, n0 = (wid & 3) * 32;
    int g = lane >> 2, t4 = lane & 3;
    uint32_t aAddrBase = smb + SM_A + ((m0 + (lane & 15)) * PAD + (lane >> 4) * 8) * 2;

    // ---- GEMM1 ----
    float c[2][4][4];
    #pragma unroll
    for (int mi = 0; mi < 2; mi++)
        #pragma unroll
        for (int ni = 0; ni < 4; ni++)
            #pragma unroll
            for (int q = 0; q < 4; q++) c[mi][ni][q] = 0.f;

    #pragma unroll
    for (int kc = 0; kc < 8; kc++) {
        uint32_t a[2][4];
        ldmatrix4(a[0], aAddrBase + kc * 32);
        ldmatrix4(a[1], aAddrBase + 16 * PAD * 2 + kc * 32);
        #pragma unroll
        for (int ni = 0; ni < 4; ni++) {
            const char* bp = sm + SM_W1 + ((n0 + ni * 8 + g) * PAD + kc * 16 + t4 * 2) * 2;
            uint32_t b0 = *(const uint32_t*)bp;
            uint32_t b1r = *(const uint32_t*)(bp + 16);
            mma16816(c[0][ni], a[0], b0, b1r);
            mma16816(c[1][ni], a[1], b0, b1r);
        }
    }

    float hn[2][4][4];
    #pragma unroll
    for (int ni = 0; ni < 4; ni++) {
        int col = n0 + ni * 8 + t4 * 2;
        float bb0 = ((const float*)(sm + SM_B1))[col];
        float bb1 = ((const float*)(sm + SM_B1))[col + 1];
        #pragma unroll
        for (int mi = 0; mi < 2; mi++) {
            hn[mi][ni][0] = c[mi][ni][0] + bb0;
            hn[mi][ni][1] = c[mi][ni][1] + bb1;
            hn[mi][ni][2] = c[mi][ni][2] + bb0;
            hn[mi][ni][3] = c[mi][ni][3] + bb1;
        }
    }
    __syncthreads();

    // ---- prod tile ----
    #pragma unroll
    for (int mi = 0; mi < 2; mi++) {
        int rlo = m0 + mi * 16 + g, rhi = rlo + 8;
        int glo = row0 + rlo, ghi = row0 + rhi;
        #pragma unroll
        for (int ni = 0; ni < 4; ni++) {
            int col = n0 + ni * 8 + t4 * 2;
            float2 flo = make_float2(0.f, 0.f), fhi = make_float2(0.f, 0.f);
            if (glo < N) flo = *(const float2*)(feat + (size_t)glo * DIM + col);
            if (ghi < N) fhi = *(const float2*)(feat + (size_t)ghi * DIM + col);
            __half2 plo = __floats2half2_rn(flo.x * hn[mi][ni][0], flo.y * hn[mi][ni][1]);
            __half2 phi = __floats2half2_rn(fhi.x * hn[mi][ni][2], fhi.y * hn[mi][ni][3]);
            *(__half2*)(sm + SM_A + (rlo * PAD + col) * 2) = plo;
            *(__half2*)(sm + SM_A + (rhi * PAD + col) * 2) = phi;
        }
    }
    __syncthreads();

    // ---- GEMM2 ----
    #pragma unroll
    for (int mi = 0; mi < 2; mi++)
        #pragma unroll
        for (int ni = 0; ni < 4; ni++)
            #pragma unroll
            for (int q = 0; q < 4; q++) c[mi][ni][q] = 0.f;

    #pragma unroll
    for (int kc = 0; kc < 8; kc++) {
        uint32_t a[2][4];
        ldmatrix4(a[0], aAddrBase + kc * 32);
        ldmatrix4(a[1], aAddrBase + 16 * PAD * 2 + kc * 32);
        #pragma unroll
        for (int ni = 0; ni < 4; ni++) {
            const char* bp = sm + SM_W2 + ((n0 + ni * 8 + g) * PAD + kc * 16 + t4 * 2) * 2;
            uint32_t b0 = *(const uint32_t*)bp;
            uint32_t b1r = *(const uint32_t*)(bp + 16);
            mma16816(c[0][ni], a[0], b0, b1r);
            mma16816(c[1][ni], a[1], b0, b1r);
        }
    }

    // ---- epilogue ----
    #pragma unroll
    for (int mi = 0; mi < 2; mi++) {
        int rlo = m0 + mi * 16 + g, rhi = rlo + 8;
        int glo = row0 + rlo, ghi = row0 + rhi;
        #pragma unroll
        for (int ni = 0; ni < 4; ni++) {
            int col = n0 + ni * 8 + t4 * 2;
            float bb0 = ((const float*)(sm + SM_B2))[col];
            float bb1 = ((const float*)(sm + SM_B2))[col + 1];
            if (glo < N) {
                float2 f = *(const float2*)(feat + (size_t)glo * DIM + col);
                float2 o;
                o.x = lrelu(c[mi][ni][0] + bb0 + f.x + hn[mi][ni][0]);
                o.y = lrelu(c[mi][ni][1] + bb1 + f.y + hn[mi][ni][1]);
                *(float2*)(out + (size_t)glo * DIM + col) = o;
            }
            if (ghi < N) {
                float2 f = *(const float2*)(feat + (size_t)ghi * DIM + col);
                float2 o;
                o.x = lrelu(c[mi][ni][2] + bb0 + f.x + hn[mi][ni][2]);
                o.y = lrelu(c[mi][ni][3] + bb1 + f.y + hn[mi][ni][3]);
                *(float2*)(out + (size_t)ghi * DIM + col) = o;
            }
        }
    }
}

// ---------------- launch ----------------
extern "C" void kernel_launch(void* const* d_in, const int* in_sizes, int n_in,
                              void* d_out, int out_size) {
    const int*   indices  = (const int*)d_in[0];
    const float* features = (const float*)d_in[1];
    const float* W1_w   = (const float*)d_in[3];
    const float* W1_b   = (const float*)d_in[4];
    const float* W2_w   = (const float*)d_in[5];
    const float* W2_b   = (const float*)d_in[6];
    const float* Watt_w = (const float*)d_in[7];
    const float* Watt_b = (const float*)d_in[8];
    const float* a_vec  = (const float*)d_in[9];

    int E = in_sizes[0] / 2;
    int N = in_sizes[1] / DIM;

    cudaFuncSetAttribute((const void*)k_gemm,
                         cudaFuncAttributeMaxDynamicSharedMemorySize, SMEMF);

    float* out = (float*)d_out;

    // slot 1
    k_attw<<<17, 256>>>(Watt_w, Watt_b, a_vec, W1_w, W2_w);
    // slot 2
    k_node_scores<<<(N * 32 + 255) / 256, 256>>>(features, N);
    // slot 3
    k_fill<<<(E + 255) / 256, 256>>>(indices, E);
    // slot 4 (profiled)
    k_aggregate<<<(N * 32 + 255) / 256, 256>>>(N);
    // slot 5
    k_gemm<<<(N + 127) / 128, 512, SMEMF>>>(features, W1_b, W2_b, out, N);
}